// round 1
// baseline (speedup 1.0000x reference)
#include <cuda_runtime.h>
#include <cuda_bf16.h>

#define HDIM 64
#define NLAYERS 3
#define EPSV 1e-5f
#define NMAX 100000
#define EMAX 3200000
#define FIN 12

// ---------------- scratch (device globals; no allocations allowed) ----------
__device__ __align__(256) int   g_src[EMAX];
__device__ __align__(256) int   g_dst[EMAX];
__device__ __align__(256) float g_norm[EMAX];
__device__ __align__(256) float g_dinv[NMAX];          // deg -> dinv in place
__device__ __align__(256) float g_hA[NMAX * HDIM];     // current h
__device__ __align__(256) float g_hB[NMAX * HDIM];     // h @ W
__device__ __align__(256) float g_hC[NMAX * HDIM];     // aggregated
__device__ float g_sum[HDIM];
__device__ float g_sumsq[HDIM];
__device__ int   g_isI32;

// ---------------- init: deg = 1 (self loop) --------------------------------
__global__ void k_init_deg(int N) {
    int i = blockIdx.x * blockDim.x + threadIdx.x;
    if (i < N) g_dinv[i] = 1.0f;
}

// ---------------- edge dtype detection -------------------------------------
// If edge_index is int64, every odd 32-bit word is a high half == 0 (ids < 2^31).
// If int32, odd words are random node ids (virtually never all zero over 4K samples).
__global__ void k_detect(const unsigned int* __restrict__ w, int nwords) {
    __shared__ int any;
    if (threadIdx.x == 0) any = 0;
    __syncthreads();
    int found = 0;
    for (int i = threadIdx.x; i < nwords; i += blockDim.x)
        if ((i & 1) && w[i] != 0u) found = 1;
    if (found) any = 1;
    __syncthreads();
    if (threadIdx.x == 0) g_isI32 = any;
}

// ---------------- convert edges to int32 + degree histogram ----------------
__global__ void k_convert(const unsigned int* __restrict__ w, int E) {
    int e = blockIdx.x * blockDim.x + threadIdx.x;
    if (e >= E) return;
    int s, d;
    if (g_isI32) {
        s = (int)w[e];
        d = (int)w[E + e];
    } else {
        s = (int)w[2 * e];          // low word of int64 src[e]
        d = (int)w[2 * E + 2 * e];  // low word of int64 dst[e]
    }
    g_src[e] = s;
    g_dst[e] = d;
    atomicAdd(&g_dinv[d], 1.0f);
}

__global__ void k_dinv(int N) {
    int i = blockIdx.x * blockDim.x + threadIdx.x;
    if (i < N) g_dinv[i] = rsqrtf(g_dinv[i]);
}

__global__ void k_norme(int E) {
    int e = blockIdx.x * blockDim.x + threadIdx.x;
    if (e < E) g_norm[e] = g_dinv[g_src[e]] * g_dinv[g_dst[e]];
}

// ---------------- input MLP: h = relu(x @ W_in + b_in) ----------------------
__global__ void k_input(const float* __restrict__ x, const float* __restrict__ Win,
                        const float* __restrict__ bin, int N) {
    __shared__ float Ws[FIN * HDIM];
    __shared__ float bs[HDIM];
    __shared__ float xs[4 * FIN];
    int tid = threadIdx.x;
    for (int i = tid; i < FIN * HDIM; i += 256) Ws[i] = Win[i];
    if (tid < HDIM) bs[tid] = bin[tid];
    int node0 = blockIdx.x * 4;
    if (tid < 4 * FIN) {
        int ln = tid / FIN, k = tid % FIN;
        int n = node0 + ln;
        xs[tid] = (n < N) ? x[n * FIN + k] : 0.0f;
    }
    __syncthreads();
    int ln = tid >> 6, j = tid & 63;
    int node = node0 + ln;
    if (node < N) {
        float acc = bs[j];
#pragma unroll
        for (int k = 0; k < FIN; k++) acc += xs[ln * FIN + k] * Ws[k * HDIM + j];
        g_hA[node * HDIM + j] = fmaxf(acc, 0.0f);
    }
}

// ---------------- per-layer GEMM: hB = hA @ W  (64x64) ----------------------
__global__ void k_gemm(const float* __restrict__ W, int N) {
    __shared__ float Ws[HDIM * HDIM];   // 16 KB
    __shared__ float hs[16 * HDIM];     // 4 KB
    int tid = threadIdx.x;
    const float4* W4 = (const float4*)W;
    float4* Ws4 = (float4*)Ws;
    for (int i = tid; i < HDIM * HDIM / 4; i += 256) Ws4[i] = W4[i];
    int node0 = blockIdx.x * 16;
    int cnt = min(16, N - node0);
    const float4* h4 = (const float4*)&g_hA[(size_t)node0 * HDIM];
    float4* hs4 = (float4*)hs;
    for (int i = tid; i < cnt * HDIM / 4; i += 256) hs4[i] = h4[i];
    __syncthreads();
    int g = tid >> 6, j = tid & 63;
    float a0 = 0.f, a1 = 0.f, a2 = 0.f, a3 = 0.f;
#pragma unroll 8
    for (int k = 0; k < HDIM; k++) {
        float wv = Ws[k * HDIM + j];
        a0 += hs[(g * 4 + 0) * HDIM + k] * wv;
        a1 += hs[(g * 4 + 1) * HDIM + k] * wv;
        a2 += hs[(g * 4 + 2) * HDIM + k] * wv;
        a3 += hs[(g * 4 + 3) * HDIM + k] * wv;
    }
    int r = node0 + g * 4;
    if (r + 0 < N) g_hB[(size_t)(r + 0) * HDIM + j] = a0;
    if (r + 1 < N) g_hB[(size_t)(r + 1) * HDIM + j] = a1;
    if (r + 2 < N) g_hB[(size_t)(r + 2) * HDIM + j] = a2;
    if (r + 3 < N) g_hB[(size_t)(r + 3) * HDIM + j] = a3;
}

// ---------------- init agg: hC = hB * self_norm + b; zero BN sums -----------
__global__ void k_initagg(const float* __restrict__ b, int N) {
    int idx = blockIdx.x * blockDim.x + threadIdx.x;
    if (blockIdx.x == 0 && threadIdx.x < 2 * HDIM) {
        if (threadIdx.x < HDIM) g_sum[threadIdx.x] = 0.0f;
        else g_sumsq[threadIdx.x - HDIM] = 0.0f;
    }
    if (idx >= N * HDIM) return;
    int i = idx >> 6, j = idx & 63;
    float di = g_dinv[i];
    g_hC[idx] = g_hB[idx] * di * di + b[j];
}

// ---------------- edge scatter: hC[dst] += norm_e * hB[src] -----------------
// 16 threads / edge, float4 gather, vectorized red.global.add.v4.f32
__global__ void k_scatter(int E) {
    int idx = blockIdx.x * blockDim.x + threadIdx.x;
    int e = idx >> 4;
    if (e >= E) return;
    int t = idx & 15;
    int s = g_src[e];
    int d = g_dst[e];
    float w = g_norm[e];
    float4 v = *(const float4*)&g_hB[(size_t)s * HDIM + t * 4];
    float* out = &g_hC[(size_t)d * HDIM + t * 4];
    float x0 = v.x * w, x1 = v.y * w, x2 = v.z * w, x3 = v.w * w;
    asm volatile("red.global.add.v4.f32 [%0], {%1, %2, %3, %4};"
                 :: "l"(out), "f"(x0), "f"(x1), "f"(x2), "f"(x3)
                 : "memory");
}

// ---------------- BN stats: per-feature sum / sumsq over N ------------------
__global__ void k_bnstats(int N) {
    __shared__ float ss[256];
    __shared__ float ss2[256];
    int tid = threadIdx.x;
    int g = tid >> 6, j = tid & 63;
    float s = 0.f, s2 = 0.f;
    for (int node = blockIdx.x * 4 + g; node < N; node += gridDim.x * 4) {
        float v = g_hC[(size_t)node * HDIM + j];
        s += v;
        s2 += v * v;
    }
    ss[tid] = s;
    ss2[tid] = s2;
    __syncthreads();
    if (tid < HDIM) {
        float a  = ss[tid]  + ss[tid + 64]  + ss[tid + 128]  + ss[tid + 192];
        float a2 = ss2[tid] + ss2[tid + 64] + ss2[tid + 128] + ss2[tid + 192];
        atomicAdd(&g_sum[tid], a);
        atomicAdd(&g_sumsq[tid], a2);
    }
}

// ---------------- BN apply (+ optional relu): hA = BN(hC) -------------------
__global__ void k_bnapply(const float* __restrict__ gamma, const float* __restrict__ beta,
                          int N, int doRelu) {
    int idx = blockIdx.x * blockDim.x + threadIdx.x;
    if (idx >= N * HDIM) return;
    int j = idx & 63;
    float invN = 1.0f / (float)N;
    float mu = g_sum[j] * invN;
    float var = g_sumsq[j] * invN - mu * mu;
    float sc = gamma[j] * rsqrtf(var + EPSV);
    float v = (g_hC[idx] - mu) * sc + beta[j];
    if (doRelu) v = fmaxf(v, 0.0f);
    g_hA[idx] = v;
}

// ---------------- classifier: out = relu(hA@Wc1+b1) @ Wc2 + b2 --------------
__global__ void k_cls(const float* __restrict__ Wc1, const float* __restrict__ bc1,
                      const float* __restrict__ Wc2, const float* __restrict__ bc2,
                      float* __restrict__ out, int N) {
    __shared__ float W1[HDIM * 32];     // 8 KB
    __shared__ float b1[32];
    __shared__ float W2[32 * 2];
    __shared__ float b2v[2];
    __shared__ float hs[128 * 65];      // padded stride -> conflict-free
    int tid = threadIdx.x;
    for (int i = tid; i < HDIM * 32; i += 128) W1[i] = Wc1[i];
    if (tid < 32) b1[tid] = bc1[tid];
    if (tid < 64) W2[tid] = Wc2[tid];
    if (tid < 2)  b2v[tid] = bc2[tid];
    int node0 = blockIdx.x * 128;
    int cnt = min(128, N - node0);
    for (int i = tid; i < cnt * HDIM; i += 128) {
        int r = i >> 6, k = i & 63;
        hs[r * 65 + k] = g_hA[(size_t)(node0 + r) * HDIM + k];
    }
    __syncthreads();
    int node = node0 + tid;
    if (node < N) {
        float o0 = b2v[0], o1 = b2v[1];
        const float* hr = &hs[tid * 65];
        for (int jj = 0; jj < 32; jj++) {
            float a = b1[jj];
#pragma unroll 8
            for (int k = 0; k < HDIM; k++) a += hr[k] * W1[k * 32 + jj];
            a = fmaxf(a, 0.0f);
            o0 += a * W2[jj * 2 + 0];
            o1 += a * W2[jj * 2 + 1];
        }
        out[node * 2 + 0] = o0;
        out[node * 2 + 1] = o1;
    }
}

// ---------------- launch -----------------------------------------------------
extern "C" void kernel_launch(void* const* d_in, const int* in_sizes, int n_in,
                              void* d_out, int out_size) {
    const float*        x     = (const float*)d_in[0];
    const unsigned int* ei    = (const unsigned int*)d_in[1];   // dtype detected on device
    const float*        Win   = (const float*)d_in[2];
    const float*        bin   = (const float*)d_in[3];
    const float*        Wg    = (const float*)d_in[4];
    const float*        bg    = (const float*)d_in[5];
    const float*        gamma = (const float*)d_in[6];
    const float*        beta  = (const float*)d_in[7];
    const float*        Wc1   = (const float*)d_in[8];
    const float*        bc1   = (const float*)d_in[9];
    const float*        Wc2   = (const float*)d_in[10];
    const float*        bc2   = (const float*)d_in[11];
    float*              out   = (float*)d_out;

    int N = in_sizes[0] / FIN;
    int E = in_sizes[1] / 2;
    if (N > NMAX) N = NMAX;
    if (E > EMAX) E = EMAX;

    int gN   = (N + 255) / 256;
    int gE   = (E + 255) / 256;
    int gNH  = (N * HDIM + 255) / 256;

    k_init_deg<<<gN, 256>>>(N);
    {
        int nwords = 2 * E;
        if (nwords > 8192) nwords = 8192;
        k_detect<<<1, 256>>>(ei, nwords);
    }
    k_convert<<<gE, 256>>>(ei, E);
    k_dinv<<<gN, 256>>>(N);
    k_norme<<<gE, 256>>>(E);

    k_input<<<(N + 3) / 4, 256>>>(x, Win, bin, N);

    for (int L = 0; L < NLAYERS; L++) {
        k_gemm<<<(N + 15) / 16, 256>>>(Wg + L * HDIM * HDIM, N);
        k_initagg<<<gNH, 256>>>(bg + L * HDIM, N);
        long long sthreads = (long long)E * 16;
        int sblocks = (int)((sthreads + 255) / 256);
        k_scatter<<<sblocks, 256>>>(E);
        k_bnstats<<<592, 256>>>(N);
        k_bnapply<<<gNH, 256>>>(gamma + L * HDIM, beta + L * HDIM, N, (L < NLAYERS - 1) ? 1 : 0);
    }

    k_cls<<<(N + 127) / 128, 128>>>(Wc1, bc1, Wc2, bc2, out, N);
}

// round 2
// speedup vs baseline: 1.6855x; 1.6855x over previous
#include <cuda_runtime.h>
#include <cuda_bf16.h>

#define HDIM 64
#define NLAYERS 3
#define EPSV 1e-5f
#define NMAX 100000
#define EMAX 3200000
#define FIN 12
#define SCAN_B 256

// ---------------- scratch (device globals; no allocations allowed) ----------
__device__ __align__(256) int   g_src[EMAX];
__device__ __align__(256) int   g_dst[EMAX];
__device__ __align__(256) int   g_eidx[EMAX];        // CSR: src per edge, sorted by dst
__device__ __align__(256) int   g_cnt[NMAX];
__device__ __align__(256) int   g_rowptr[NMAX + 1];
__device__ __align__(256) int   g_cursor[NMAX];
__device__ int   g_bsum[512];
__device__ __align__(256) float g_dinv[NMAX];
__device__ __align__(256) float g_hA[NMAX * HDIM];   // input-MLP output
__device__ __align__(256) float g_hB[NMAX * HDIM];   // h @ W
__device__ __align__(256) float g_hC[NMAX * HDIM];   // aggregated (pre-BN)
__device__ float g_sum[NLAYERS * HDIM];
__device__ float g_sumsq[NLAYERS * HDIM];
__device__ int   g_isI32;

// ---------------- zero counters ---------------------------------------------
__global__ void k_zero(int N) {
    int i = blockIdx.x * blockDim.x + threadIdx.x;
    if (i < N) g_cnt[i] = 0;
    if (i < NLAYERS * HDIM) { g_sum[i] = 0.0f; g_sumsq[i] = 0.0f; }
}

// ---------------- edge dtype detection --------------------------------------
__global__ void k_detect(const unsigned int* __restrict__ w, int nwords) {
    __shared__ int any;
    if (threadIdx.x == 0) any = 0;
    __syncthreads();
    int found = 0;
    for (int i = threadIdx.x; i < nwords; i += blockDim.x)
        if ((i & 1) && w[i] != 0u) found = 1;
    if (found) any = 1;
    __syncthreads();
    if (threadIdx.x == 0) g_isI32 = any;
}

// ---------------- convert edges to int32 + dst histogram --------------------
__global__ void k_convert(const unsigned int* __restrict__ w, int E) {
    int e = blockIdx.x * blockDim.x + threadIdx.x;
    if (e >= E) return;
    int s, d;
    if (g_isI32) { s = (int)w[e];     d = (int)w[E + e]; }
    else         { s = (int)w[2 * e]; d = (int)w[2 * E + 2 * e]; }
    g_src[e] = s;
    g_dst[e] = d;
    atomicAdd(&g_cnt[d], 1);
}

__global__ void k_dinv(int N) {
    int i = blockIdx.x * blockDim.x + threadIdx.x;
    if (i < N) g_dinv[i] = rsqrtf((float)g_cnt[i] + 1.0f);
}

// ---------------- 2-level exclusive scan of g_cnt -> g_rowptr ----------------
__global__ void k_scanA(int N) {
    __shared__ int sh[SCAN_B];
    int tid = threadIdx.x;
    int i = blockIdx.x * SCAN_B + tid;
    sh[tid] = (i < N) ? g_cnt[i] : 0;
    __syncthreads();
#pragma unroll
    for (int off = 1; off < SCAN_B; off <<= 1) {
        int t = (tid >= off) ? sh[tid - off] : 0;
        __syncthreads();
        sh[tid] += t;
        __syncthreads();
    }
    if (i < N) g_rowptr[i + 1] = sh[tid];
    if (tid == SCAN_B - 1) g_bsum[blockIdx.x] = sh[tid];
}
__global__ void k_scanB(int nblocks) {
    __shared__ int sh[512];
    int tid = threadIdx.x;
    sh[tid] = (tid < nblocks) ? g_bsum[tid] : 0;
    __syncthreads();
#pragma unroll
    for (int off = 1; off < 512; off <<= 1) {
        int t = (tid >= off) ? sh[tid - off] : 0;
        __syncthreads();
        sh[tid] += t;
        __syncthreads();
    }
    if (tid < nblocks) g_bsum[tid] = sh[tid];
}
__global__ void k_scanC(int N) {
    int i = blockIdx.x * blockDim.x + threadIdx.x;
    if (i == 0) g_rowptr[0] = 0;
    if (i < N) {
        int b = i >> 8;
        int add = (b == 0) ? 0 : g_bsum[b - 1];
        g_rowptr[i + 1] += add;
    }
}
__global__ void k_cursor(int N) {
    int i = blockIdx.x * blockDim.x + threadIdx.x;
    if (i < N) g_cursor[i] = g_rowptr[i];
}
__global__ void k_fill(int E) {
    int e = blockIdx.x * blockDim.x + threadIdx.x;
    if (e >= E) return;
    int d = g_dst[e];
    int pos = atomicAdd(&g_cursor[d], 1);
    g_eidx[pos] = g_src[e];
}

// ---------------- input MLP: hA = relu(x @ W_in + b_in) ----------------------
__global__ void k_input(const float* __restrict__ x, const float* __restrict__ Win,
                        const float* __restrict__ bin, int N) {
    __shared__ float Ws[FIN * HDIM];
    __shared__ float bs[HDIM];
    __shared__ float xs[4 * FIN];
    int tid = threadIdx.x;
    for (int i = tid; i < FIN * HDIM; i += 256) Ws[i] = Win[i];
    if (tid < HDIM) bs[tid] = bin[tid];
    int node0 = blockIdx.x * 4;
    if (tid < 4 * FIN) {
        int ln = tid / FIN, k = tid % FIN;
        int n = node0 + ln;
        xs[tid] = (n < N) ? x[n * FIN + k] : 0.0f;
    }
    __syncthreads();
    int ln = tid >> 6, j = tid & 63;
    int node = node0 + ln;
    if (node < N) {
        float acc = bs[j];
#pragma unroll
        for (int k = 0; k < FIN; k++) acc += xs[ln * FIN + k] * Ws[k * HDIM + j];
        g_hA[node * HDIM + j] = fmaxf(acc, 0.0f);
    }
}

// ---------------- GEMM with fused BN(+relu) on input load -------------------
// bnmode: 0 = read g_hA raw (layer 0); 1 = read g_hC with BN+relu (stats Lprev)
__global__ void k_gemm(const float* __restrict__ W,
                       const float* __restrict__ gamma, const float* __restrict__ beta,
                       int Lprev, int bnmode, int N) {
    __shared__ float Ws[HDIM * HDIM];
    __shared__ float hs[16 * HDIM];
    __shared__ float s_mu[HDIM], s_sc[HDIM], s_bt[HDIM];
    int tid = threadIdx.x;
    const float4* W4 = (const float4*)W;
    float4* Ws4 = (float4*)Ws;
    for (int i = tid; i < HDIM * HDIM / 4; i += 256) Ws4[i] = W4[i];
    if (bnmode && tid < HDIM) {
        float invN = 1.0f / (float)N;
        float mu = g_sum[Lprev * HDIM + tid] * invN;
        float var = g_sumsq[Lprev * HDIM + tid] * invN - mu * mu;
        s_mu[tid] = mu;
        s_sc[tid] = gamma[Lprev * HDIM + tid] * rsqrtf(var + EPSV);
        s_bt[tid] = beta[Lprev * HDIM + tid];
    }
    int node0 = blockIdx.x * 16;
    int cnt = min(16, N - node0);
    __syncthreads();
    const float* in = bnmode ? g_hC : g_hA;
    const float4* h4 = (const float4*)&in[(size_t)node0 * HDIM];
    float4* hs4 = (float4*)hs;
    for (int i = tid; i < cnt * HDIM / 4; i += 256) {
        float4 v = h4[i];
        if (bnmode) {
            int j = (i & 15) * 4;
            v.x = fmaxf((v.x - s_mu[j + 0]) * s_sc[j + 0] + s_bt[j + 0], 0.0f);
            v.y = fmaxf((v.y - s_mu[j + 1]) * s_sc[j + 1] + s_bt[j + 1], 0.0f);
            v.z = fmaxf((v.z - s_mu[j + 2]) * s_sc[j + 2] + s_bt[j + 2], 0.0f);
            v.w = fmaxf((v.w - s_mu[j + 3]) * s_sc[j + 3] + s_bt[j + 3], 0.0f);
        }
        hs4[i] = v;
    }
    __syncthreads();
    int g = tid >> 6, j = tid & 63;
    float a0 = 0.f, a1 = 0.f, a2 = 0.f, a3 = 0.f;
#pragma unroll 8
    for (int k = 0; k < HDIM; k++) {
        float wv = Ws[k * HDIM + j];
        a0 += hs[(g * 4 + 0) * HDIM + k] * wv;
        a1 += hs[(g * 4 + 1) * HDIM + k] * wv;
        a2 += hs[(g * 4 + 2) * HDIM + k] * wv;
        a3 += hs[(g * 4 + 3) * HDIM + k] * wv;
    }
    int r = node0 + g * 4;
    if (r + 0 < N) g_hB[(size_t)(r + 0) * HDIM + j] = a0;
    if (r + 1 < N) g_hB[(size_t)(r + 1) * HDIM + j] = a1;
    if (r + 2 < N) g_hB[(size_t)(r + 2) * HDIM + j] = a2;
    if (r + 3 < N) g_hB[(size_t)(r + 3) * HDIM + j] = a3;
}

// ---------------- pull aggregation + self-loop + bias + BN stats ------------
// one warp per dst node; thread t owns features [2t, 2t+1]
__global__ void k_agg(const float* __restrict__ bg, int L, int N) {
    __shared__ float s_s[HDIM];
    __shared__ float s_q[HDIM];
    int tid = threadIdx.x;
    int lane = tid & 31;
    int warp = tid >> 5;
    if (tid < HDIM) { s_s[tid] = 0.0f; s_q[tid] = 0.0f; }
    __syncthreads();
    int node = blockIdx.x * 8 + warp;
    if (node < N) {
        int r0 = g_rowptr[node];
        int r1 = g_rowptr[node + 1];
        float ddst = g_dinv[node];
        const float2* hB2 = (const float2*)g_hB;
        float ax = 0.0f, ay = 0.0f;
        int s_next = (r0 < r1) ? __ldg(&g_eidx[r0]) : 0;
        for (int i = r0; i < r1; i++) {
            int s_cur = s_next;
            if (i + 1 < r1) s_next = __ldg(&g_eidx[i + 1]);
            float w = __ldg(&g_dinv[s_cur]);
            float2 v = __ldg(&hB2[(size_t)s_cur * 32 + lane]);
            ax += w * v.x;
            ay += w * v.y;
        }
        float2 hv = hB2[(size_t)node * 32 + lane];
        float sn = ddst * ddst;
        ax = ax * ddst + hv.x * sn + bg[L * HDIM + 2 * lane];
        ay = ay * ddst + hv.y * sn + bg[L * HDIM + 2 * lane + 1];
        ((float2*)g_hC)[(size_t)node * 32 + lane] = make_float2(ax, ay);
        atomicAdd(&s_s[2 * lane],     ax);
        atomicAdd(&s_s[2 * lane + 1], ay);
        atomicAdd(&s_q[2 * lane],     ax * ax);
        atomicAdd(&s_q[2 * lane + 1], ay * ay);
    }
    __syncthreads();
    if (tid < HDIM) {
        atomicAdd(&g_sum[L * HDIM + tid],   s_s[tid]);
        atomicAdd(&g_sumsq[L * HDIM + tid], s_q[tid]);
    }
}

// ---------------- classifier with fused BN (no relu) on load ----------------
__global__ void k_cls(const float* __restrict__ Wc1, const float* __restrict__ bc1,
                      const float* __restrict__ Wc2, const float* __restrict__ bc2,
                      const float* __restrict__ gamma, const float* __restrict__ beta,
                      float* __restrict__ out, int N) {
    __shared__ float W1[HDIM * 32];
    __shared__ float b1[32];
    __shared__ float W2[32 * 2];
    __shared__ float b2v[2];
    __shared__ float s_mu[HDIM], s_sc[HDIM], s_bt[HDIM];
    __shared__ float hs[128 * 65];
    int tid = threadIdx.x;
    for (int i = tid; i < HDIM * 32; i += 128) W1[i] = Wc1[i];
    if (tid < 32) b1[tid] = bc1[tid];
    if (tid < 64) W2[tid] = Wc2[tid];
    if (tid < 2)  b2v[tid] = bc2[tid];
    if (tid < HDIM) {
        int Lp = NLAYERS - 1;
        float invN = 1.0f / (float)N;
        float mu = g_sum[Lp * HDIM + tid] * invN;
        float var = g_sumsq[Lp * HDIM + tid] * invN - mu * mu;
        s_mu[tid] = mu;
        s_sc[tid] = gamma[Lp * HDIM + tid] * rsqrtf(var + EPSV);
        s_bt[tid] = beta[Lp * HDIM + tid];
    }
    int node0 = blockIdx.x * 128;
    int cnt = min(128, N - node0);
    __syncthreads();
    for (int i = tid; i < cnt * HDIM; i += 128) {
        int r = i >> 6, k = i & 63;
        float v = g_hC[(size_t)(node0 + r) * HDIM + k];
        hs[r * 65 + k] = (v - s_mu[k]) * s_sc[k] + s_bt[k];
    }
    __syncthreads();
    int node = node0 + tid;
    if (node < N) {
        float o0 = b2v[0], o1 = b2v[1];
        const float* hr = &hs[tid * 65];
        for (int jj = 0; jj < 32; jj++) {
            float a = b1[jj];
#pragma unroll 8
            for (int k = 0; k < HDIM; k++) a += hr[k] * W1[k * 32 + jj];
            a = fmaxf(a, 0.0f);
            o0 += a * W2[jj * 2 + 0];
            o1 += a * W2[jj * 2 + 1];
        }
        out[node * 2 + 0] = o0;
        out[node * 2 + 1] = o1;
    }
}

// ---------------- launch -----------------------------------------------------
extern "C" void kernel_launch(void* const* d_in, const int* in_sizes, int n_in,
                              void* d_out, int out_size) {
    const float*        x     = (const float*)d_in[0];
    const unsigned int* ei    = (const unsigned int*)d_in[1];
    const float*        Win   = (const float*)d_in[2];
    const float*        bin   = (const float*)d_in[3];
    const float*        Wg    = (const float*)d_in[4];
    const float*        bg    = (const float*)d_in[5];
    const float*        gamma = (const float*)d_in[6];
    const float*        beta  = (const float*)d_in[7];
    const float*        Wc1   = (const float*)d_in[8];
    const float*        bc1   = (const float*)d_in[9];
    const float*        Wc2   = (const float*)d_in[10];
    const float*        bc2   = (const float*)d_in[11];
    float*              out   = (float*)d_out;

    int N = in_sizes[0] / FIN;
    int E = in_sizes[1] / 2;
    if (N > NMAX) N = NMAX;
    if (E > EMAX) E = EMAX;

    int gN = (N + 255) / 256;
    int gE = (E + 255) / 256;
    int nblocks = (N + SCAN_B - 1) / SCAN_B;

    // ---- preprocessing: CSR build ----
    k_zero<<<gN, 256>>>(N);
    {
        int nwords = 2 * E;
        if (nwords > 8192) nwords = 8192;
        k_detect<<<1, 256>>>(ei, nwords);
    }
    k_convert<<<gE, 256>>>(ei, E);
    k_dinv<<<gN, 256>>>(N);
    k_scanA<<<nblocks, SCAN_B>>>(N);
    k_scanB<<<1, 512>>>(nblocks);
    k_scanC<<<gN, 256>>>(N);
    k_cursor<<<gN, 256>>>(N);
    k_fill<<<gE, 256>>>(E);

    // ---- network ----
    k_input<<<(N + 3) / 4, 256>>>(x, Win, bin, N);
    for (int L = 0; L < NLAYERS; L++) {
        k_gemm<<<(N + 15) / 16, 256>>>(Wg + L * HDIM * HDIM, gamma, beta,
                                       L - 1, (L == 0) ? 0 : 1, N);
        k_agg<<<(N + 7) / 8, 256>>>(bg, L, N);
    }
    k_cls<<<(N + 127) / 128, 128>>>(Wc1, bc1, Wc2, bc2, gamma, beta, out, N);
}

// round 3
// speedup vs baseline: 2.0170x; 1.1966x over previous
#include <cuda_runtime.h>
#include <cuda_fp16.h>

#define HDIM 64
#define NLAYERS 3
#define EPSV 1e-5f
#define NMAX 100000
#define EMAX 3200000
#define FIN 12
#define SCAN_B 256

// ---------------- scratch (device globals; no allocations allowed) ----------
__device__ __align__(256) int    g_src[EMAX];
__device__ __align__(256) int    g_dst[EMAX];
__device__ __align__(256) int    g_eidx[EMAX];        // CSR: src per edge, sorted by dst
__device__ __align__(256) int    g_cnt[NMAX];
__device__ __align__(256) int    g_rowptr[NMAX + 1];
__device__ __align__(256) int    g_cursor[NMAX];
__device__ int    g_bsum[512];
__device__ __align__(256) float  g_dinv[NMAX];
__device__ __align__(256) float  g_hA[NMAX * HDIM];   // input-MLP output (fp32)
__device__ __align__(256) __half g_hBh[NMAX * HDIM];  // dinv[row]*(h@W) in fp16
__device__ __align__(256) float  g_hC[NMAX * HDIM];   // aggregated (pre-BN, fp32)
__device__ float g_sum[NLAYERS * HDIM];
__device__ float g_sumsq[NLAYERS * HDIM];
__device__ int   g_isI32;

// ---------------- zero counters ---------------------------------------------
__global__ void k_zero(int N) {
    int i = blockIdx.x * blockDim.x + threadIdx.x;
    if (i < N) g_cnt[i] = 0;
    if (i < NLAYERS * HDIM) { g_sum[i] = 0.0f; g_sumsq[i] = 0.0f; }
}

// ---------------- edge dtype detection --------------------------------------
__global__ void k_detect(const unsigned int* __restrict__ w, int nwords) {
    __shared__ int any;
    if (threadIdx.x == 0) any = 0;
    __syncthreads();
    int found = 0;
    for (int i = threadIdx.x; i < nwords; i += blockDim.x)
        if ((i & 1) && w[i] != 0u) found = 1;
    if (found) any = 1;
    __syncthreads();
    if (threadIdx.x == 0) g_isI32 = any;
}

// ---------------- convert edges to int32 + dst histogram --------------------
__global__ void k_convert(const unsigned int* __restrict__ w, int E) {
    int e = blockIdx.x * blockDim.x + threadIdx.x;
    if (e >= E) return;
    int s, d;
    if (g_isI32) { s = (int)w[e];     d = (int)w[E + e]; }
    else         { s = (int)w[2 * e]; d = (int)w[2 * E + 2 * e]; }
    g_src[e] = s;
    g_dst[e] = d;
    atomicAdd(&g_cnt[d], 1);
}

__global__ void k_dinv(int N) {
    int i = blockIdx.x * blockDim.x + threadIdx.x;
    if (i < N) g_dinv[i] = rsqrtf((float)g_cnt[i] + 1.0f);
}

// ---------------- 2-level exclusive scan of g_cnt -> g_rowptr ----------------
__global__ void k_scanA(int N) {
    __shared__ int sh[SCAN_B];
    int tid = threadIdx.x;
    int i = blockIdx.x * SCAN_B + tid;
    sh[tid] = (i < N) ? g_cnt[i] : 0;
    __syncthreads();
#pragma unroll
    for (int off = 1; off < SCAN_B; off <<= 1) {
        int t = (tid >= off) ? sh[tid - off] : 0;
        __syncthreads();
        sh[tid] += t;
        __syncthreads();
    }
    if (i < N) g_rowptr[i + 1] = sh[tid];
    if (tid == SCAN_B - 1) g_bsum[blockIdx.x] = sh[tid];
}
__global__ void k_scanB(int nblocks) {
    __shared__ int sh[512];
    int tid = threadIdx.x;
    sh[tid] = (tid < nblocks) ? g_bsum[tid] : 0;
    __syncthreads();
#pragma unroll
    for (int off = 1; off < 512; off <<= 1) {
        int t = (tid >= off) ? sh[tid - off] : 0;
        __syncthreads();
        sh[tid] += t;
        __syncthreads();
    }
    if (tid < nblocks) g_bsum[tid] = sh[tid];
}
__global__ void k_scanC(int N) {
    int i = blockIdx.x * blockDim.x + threadIdx.x;
    if (i == 0) g_rowptr[0] = 0;
    if (i < N) {
        int b = i >> 8;
        int add = (b == 0) ? 0 : g_bsum[b - 1];
        g_rowptr[i + 1] += add;
    }
}
__global__ void k_cursor(int N) {
    int i = blockIdx.x * blockDim.x + threadIdx.x;
    if (i < N) g_cursor[i] = g_rowptr[i];
}
__global__ void k_fill(int E) {
    int e = blockIdx.x * blockDim.x + threadIdx.x;
    if (e >= E) return;
    int d = g_dst[e];
    int pos = atomicAdd(&g_cursor[d], 1);
    g_eidx[pos] = g_src[e];
}

// ---------------- input MLP: hA = relu(x @ W_in + b_in) ----------------------
__global__ void k_input(const float* __restrict__ x, const float* __restrict__ Win,
                        const float* __restrict__ bin, int N) {
    __shared__ float Ws[FIN * HDIM];
    __shared__ float bs[HDIM];
    __shared__ float xs[4 * FIN];
    int tid = threadIdx.x;
    for (int i = tid; i < FIN * HDIM; i += 256) Ws[i] = Win[i];
    if (tid < HDIM) bs[tid] = bin[tid];
    int node0 = blockIdx.x * 4;
    if (tid < 4 * FIN) {
        int ln = tid / FIN, k = tid % FIN;
        int n = node0 + ln;
        xs[tid] = (n < N) ? x[n * FIN + k] : 0.0f;
    }
    __syncthreads();
    int ln = tid >> 6, j = tid & 63;
    int node = node0 + ln;
    if (node < N) {
        float acc = bs[j];
#pragma unroll
        for (int k = 0; k < FIN; k++) acc += xs[ln * FIN + k] * Ws[k * HDIM + j];
        g_hA[node * HDIM + j] = fmaxf(acc, 0.0f);
    }
}

// ---------------- GEMM + fused BN(+relu) on load + dinv-prescale fp16 store --
// bnmode: 0 = read g_hA raw (layer 0); 1 = read g_hC with BN+relu (stats Lprev)
// Output: g_hBh[row][:] = __half( dinv[row] * (h @ W)[row][:] )
__global__ void k_gemm(const float* __restrict__ W,
                       const float* __restrict__ gamma, const float* __restrict__ beta,
                       int Lprev, int bnmode, int N) {
    __shared__ float Ws[HDIM * HDIM];
    __shared__ float hs[16 * HDIM];
    __shared__ float s_mu[HDIM], s_sc[HDIM], s_bt[HDIM];
    int tid = threadIdx.x;
    const float4* W4 = (const float4*)W;
    float4* Ws4 = (float4*)Ws;
    for (int i = tid; i < HDIM * HDIM / 4; i += 256) Ws4[i] = W4[i];
    if (bnmode && tid < HDIM) {
        float invN = 1.0f / (float)N;
        float mu = g_sum[Lprev * HDIM + tid] * invN;
        float var = g_sumsq[Lprev * HDIM + tid] * invN - mu * mu;
        s_mu[tid] = mu;
        s_sc[tid] = gamma[Lprev * HDIM + tid] * rsqrtf(var + EPSV);
        s_bt[tid] = beta[Lprev * HDIM + tid];
    }
    int node0 = blockIdx.x * 16;
    int cnt = min(16, N - node0);
    __syncthreads();
    const float* in = bnmode ? g_hC : g_hA;
    const float4* h4 = (const float4*)&in[(size_t)node0 * HDIM];
    float4* hs4 = (float4*)hs;
    for (int i = tid; i < cnt * HDIM / 4; i += 256) {
        float4 v = h4[i];
        if (bnmode) {
            int j = (i & 15) * 4;
            v.x = fmaxf((v.x - s_mu[j + 0]) * s_sc[j + 0] + s_bt[j + 0], 0.0f);
            v.y = fmaxf((v.y - s_mu[j + 1]) * s_sc[j + 1] + s_bt[j + 1], 0.0f);
            v.z = fmaxf((v.z - s_mu[j + 2]) * s_sc[j + 2] + s_bt[j + 2], 0.0f);
            v.w = fmaxf((v.w - s_mu[j + 3]) * s_sc[j + 3] + s_bt[j + 3], 0.0f);
        }
        hs4[i] = v;
    }
    __syncthreads();
    // 8 groups of 32 lanes; group g handles rows 2g, 2g+1; lane l handles feats 2l, 2l+1
    int lane = tid & 31, grp = tid >> 5;
    int r0 = grp * 2, r1 = grp * 2 + 1;
    const float2* Ws2 = (const float2*)Ws;
    float a00 = 0.f, a01 = 0.f, a10 = 0.f, a11 = 0.f;
#pragma unroll 8
    for (int k = 0; k < HDIM; k++) {
        float2 w = Ws2[k * 32 + lane];       // feats 2l, 2l+1
        float h0 = hs[r0 * HDIM + k];        // broadcast
        float h1 = hs[r1 * HDIM + k];
        a00 += h0 * w.x; a01 += h0 * w.y;
        a10 += h1 * w.x; a11 += h1 * w.y;
    }
    int row0 = node0 + r0, row1 = node0 + r1;
    __half2* out2 = (__half2*)g_hBh;
    if (row0 < N) {
        float di = g_dinv[row0];
        out2[(size_t)row0 * 32 + lane] = __floats2half2_rn(a00 * di, a01 * di);
    }
    if (row1 < N) {
        float di = g_dinv[row1];
        out2[(size_t)row1 * 32 + lane] = __floats2half2_rn(a10 * di, a11 * di);
    }
}

// ---------------- pull aggregation + self-loop + bias + BN stats ------------
// one warp per dst node; lane t owns features [2t, 2t+1]; 128B gather per edge
__global__ void k_agg(const float* __restrict__ bg, int L, int N) {
    __shared__ float s_s[HDIM];
    __shared__ float s_q[HDIM];
    int tid = threadIdx.x;
    int lane = tid & 31;
    int warp = tid >> 5;
    if (tid < HDIM) { s_s[tid] = 0.0f; s_q[tid] = 0.0f; }
    __syncthreads();
    int node = blockIdx.x * 8 + warp;
    if (node < N) {
        int r0 = g_rowptr[node];
        int r1 = g_rowptr[node + 1];
        float ddst = g_dinv[node];
        const __half2* hB2 = (const __half2*)g_hBh;
        float ax = 0.0f, ay = 0.0f;
        int i = r0;
        for (; i + 4 <= r1; i += 4) {
            int s0 = __ldg(&g_eidx[i + 0]);
            int s1 = __ldg(&g_eidx[i + 1]);
            int s2 = __ldg(&g_eidx[i + 2]);
            int s3 = __ldg(&g_eidx[i + 3]);
            float2 v0 = __half22float2(__ldg(&hB2[(size_t)s0 * 32 + lane]));
            float2 v1 = __half22float2(__ldg(&hB2[(size_t)s1 * 32 + lane]));
            float2 v2 = __half22float2(__ldg(&hB2[(size_t)s2 * 32 + lane]));
            float2 v3 = __half22float2(__ldg(&hB2[(size_t)s3 * 32 + lane]));
            ax += (v0.x + v1.x) + (v2.x + v3.x);
            ay += (v0.y + v1.y) + (v2.y + v3.y);
        }
        for (; i < r1; i++) {
            int s = __ldg(&g_eidx[i]);
            float2 v = __half22float2(__ldg(&hB2[(size_t)s * 32 + lane]));
            ax += v.x;
            ay += v.y;
        }
        // self term: + dinv[node]*hBs[node]; whole sum scaled by ddst
        float2 hv = __half22float2(hB2[(size_t)node * 32 + lane]);
        ax = (ax + hv.x) * ddst + bg[L * HDIM + 2 * lane];
        ay = (ay + hv.y) * ddst + bg[L * HDIM + 2 * lane + 1];
        ((float2*)g_hC)[(size_t)node * 32 + lane] = make_float2(ax, ay);
        atomicAdd(&s_s[2 * lane],     ax);
        atomicAdd(&s_s[2 * lane + 1], ay);
        atomicAdd(&s_q[2 * lane],     ax * ax);
        atomicAdd(&s_q[2 * lane + 1], ay * ay);
    }
    __syncthreads();
    if (tid < HDIM) {
        atomicAdd(&g_sum[L * HDIM + tid],   s_s[tid]);
        atomicAdd(&g_sumsq[L * HDIM + tid], s_q[tid]);
    }
}

// ---------------- classifier with fused BN (no relu) on load ----------------
__global__ void k_cls(const float* __restrict__ Wc1, const float* __restrict__ bc1,
                      const float* __restrict__ Wc2, const float* __restrict__ bc2,
                      const float* __restrict__ gamma, const float* __restrict__ beta,
                      float* __restrict__ out, int N) {
    __shared__ float W1[HDIM * 32];
    __shared__ float b1[32];
    __shared__ float W2[32 * 2];
    __shared__ float b2v[2];
    __shared__ float s_mu[HDIM], s_sc[HDIM], s_bt[HDIM];
    __shared__ float hs[128 * 65];
    int tid = threadIdx.x;
    for (int i = tid; i < HDIM * 32; i += 128) W1[i] = Wc1[i];
    if (tid < 32) b1[tid] = bc1[tid];
    if (tid < 64) W2[tid] = Wc2[tid];
    if (tid < 2)  b2v[tid] = bc2[tid];
    if (tid < HDIM) {
        int Lp = NLAYERS - 1;
        float invN = 1.0f / (float)N;
        float mu = g_sum[Lp * HDIM + tid] * invN;
        float var = g_sumsq[Lp * HDIM + tid] * invN - mu * mu;
        s_mu[tid] = mu;
        s_sc[tid] = gamma[Lp * HDIM + tid] * rsqrtf(var + EPSV);
        s_bt[tid] = beta[Lp * HDIM + tid];
    }
    int node0 = blockIdx.x * 128;
    int cnt = min(128, N - node0);
    __syncthreads();
    for (int i = tid; i < cnt * HDIM; i += 128) {
        int r = i >> 6, k = i & 63;
        float v = g_hC[(size_t)(node0 + r) * HDIM + k];
        hs[r * 65 + k] = (v - s_mu[k]) * s_sc[k] + s_bt[k];
    }
    __syncthreads();
    int node = node0 + tid;
    if (node < N) {
        float o0 = b2v[0], o1 = b2v[1];
        const float* hr = &hs[tid * 65];
        for (int jj = 0; jj < 32; jj++) {
            float a = b1[jj];
#pragma unroll 8
            for (int k = 0; k < HDIM; k++) a += hr[k] * W1[k * 32 + jj];
            a = fmaxf(a, 0.0f);
            o0 += a * W2[jj * 2 + 0];
            o1 += a * W2[jj * 2 + 1];
        }
        out[node * 2 + 0] = o0;
        out[node * 2 + 1] = o1;
    }
}

// ---------------- launch -----------------------------------------------------
extern "C" void kernel_launch(void* const* d_in, const int* in_sizes, int n_in,
                              void* d_out, int out_size) {
    const float*        x     = (const float*)d_in[0];
    const unsigned int* ei    = (const unsigned int*)d_in[1];
    const float*        Win   = (const float*)d_in[2];
    const float*        bin   = (const float*)d_in[3];
    const float*        Wg    = (const float*)d_in[4];
    const float*        bg    = (const float*)d_in[5];
    const float*        gamma = (const float*)d_in[6];
    const float*        beta  = (const float*)d_in[7];
    const float*        Wc1   = (const float*)d_in[8];
    const float*        bc1   = (const float*)d_in[9];
    const float*        Wc2   = (const float*)d_in[10];
    const float*        bc2   = (const float*)d_in[11];
    float*              out   = (float*)d_out;

    int N = in_sizes[0] / FIN;
    int E = in_sizes[1] / 2;
    if (N > NMAX) N = NMAX;
    if (E > EMAX) E = EMAX;

    int gN = (N + 255) / 256;
    int gE = (E + 255) / 256;
    int nblocks = (N + SCAN_B - 1) / SCAN_B;

    // ---- preprocessing: CSR build ----
    k_zero<<<gN, 256>>>(N);
    {
        int nwords = 2 * E;
        if (nwords > 8192) nwords = 8192;
        k_detect<<<1, 256>>>(ei, nwords);
    }
    k_convert<<<gE, 256>>>(ei, E);
    k_dinv<<<gN, 256>>>(N);
    k_scanA<<<nblocks, SCAN_B>>>(N);
    k_scanB<<<1, 512>>>(nblocks);
    k_scanC<<<gN, 256>>>(N);
    k_cursor<<<gN, 256>>>(N);
    k_fill<<<gE, 256>>>(E);

    // ---- network ----
    k_input<<<(N + 3) / 4, 256>>>(x, Win, bin, N);
    for (int L = 0; L < NLAYERS; L++) {
        k_gemm<<<(N + 15) / 16, 256>>>(Wg + L * HDIM * HDIM, gamma, beta,
                                       L - 1, (L == 0) ? 0 : 1, N);
        k_agg<<<(N + 7) / 8, 256>>>(bg, L, N);
    }
    k_cls<<<(N + 127) / 128, 128>>>(Wc1, bc1, Wc2, bc2, gamma, beta, out, N);
}